// round 4
// baseline (speedup 1.0000x reference)
#include <cuda_runtime.h>
#include <cuda_bf16.h>

// Blocked affine-scan RK4 integrator, v3 (transposed-drive layout).
// x_{t+1} = A x_t + B u_t exactly.
//   t_in  : transpose u to [step][chunk] AND premultiply w = B u (float4).
//   phase1: per-chunk drive vectors, coalesced w loads, no smem in hot loop.
//   phase2: hierarchical boundary scan (1 warp) with in-kernel matrix powers.
//   phase3: replay with coalesced w loads; output transposed via smem buffer.

#define L_CHUNK 64
#define NCPAD 2048            // fixed row stride of transposed arrays (T <= 131072)
#define MAX_CHUNKS 4096

__device__ float4 g_wt[L_CHUNK * NCPAD];        // w_t, chunk-minor (2 MB, zero-init)
__device__ float  g_cd[MAX_CHUNKS][4];          // per-chunk drive vectors
__device__ float  g_cx[MAX_CHUNKS + 1][4];      // chunk start states

// ---------------------------------------------------------------------------
// fp32 RK4 step mirroring the reference arithmetic (setup/probing only)
// ---------------------------------------------------------------------------
struct FSys { float Cm[4], Km[4], Md[2], dt; };

__device__ __forceinline__ FSys mksys(const float* M, const float* C,
                                      const float* K, const float* dtp) {
    FSys m;
    m.Md[0] = M[0]; m.Md[1] = M[1];
    float C0 = C[0], C1 = C[1], C2 = C[2];
    m.Cm[0] = C0 + C1; m.Cm[1] = -C1; m.Cm[2] = -C1; m.Cm[3] = C2 + C1;
    float K0 = K[0], K1 = K[1], K2 = K[2];
    m.Km[0] = K0 + K1; m.Km[1] = -K1; m.Km[2] = -K1; m.Km[3] = K2 + K1;
    m.dt = dtp[0];
    return m;
}

__device__ void fstep(const FSys& m, float s[4], float u0, float u1) {
    float dt = m.dt;
    float y0 = s[0], y1 = s[1], v0 = s[2], v1 = s[3];
#define ACC(z0, z1, w0, w1, a0, a1)                                             \
    a0 = (u0 - (m.Cm[0]*(w0) + m.Cm[1]*(w1)) - (m.Km[0]*(z0) + m.Km[1]*(z1))) / m.Md[0]; \
    a1 = (u1 - (m.Cm[2]*(w0) + m.Cm[3]*(w1)) - (m.Km[2]*(z0) + m.Km[3]*(z1))) / m.Md[1];
    float k1a, k1b; ACC(y0, y1, v0, v1, k1a, k1b);
    float y2a = y0 + v0*dt*0.5f, y2b = y1 + v1*dt*0.5f;
    float v2a = v0 + k1a*dt*0.5f, v2b = v1 + k1b*dt*0.5f;
    float k2a, k2b; ACC(y2a, y2b, v2a, v2b, k2a, k2b);
    float y3a = y0 + v2a*dt*0.5f, y3b = y1 + v2b*dt*0.5f;
    float v3a = v0 + k2a*dt*0.5f, v3b = v1 + k2b*dt*0.5f;
    float k3a, k3b; ACC(y3a, y3b, v3a, v3b, k3a, k3b);
    float y4a = y0 + v3a*dt, y4b = y1 + v3b*dt;
    float v4a = v0 + k3a*dt, v4b = v1 + k3b*dt;
    float k4a, k4b; ACC(y4a, y4b, v4a, v4b, k4a, k4b);
    (void)y2a; (void)y2b; (void)y3a; (void)y3b; (void)y4a; (void)y4b;
    s[0] = y0 + dt/6.f * (v0 + 2.f*v2a + 2.f*v3a + v4a);
    s[1] = y1 + dt/6.f * (v1 + 2.f*v2b + 2.f*v3b + v4b);
    s[2] = v0 + dt/6.f * (k1a + 2.f*k2a + 2.f*k3a + k4a);
    s[3] = v1 + dt/6.f * (k1b + 2.f*k2b + 2.f*k3b + k4b);
#undef ACC
}

// Probe A columns into smem (threads 0..3), row-major sA[i*4+j].
__device__ __forceinline__ void probe_A(float* sA, const float* M, const float* C,
                                        const float* K, const float* dtp, int t) {
    if (t < 4) {
        FSys m = mksys(M, C, K, dtp);
        float s[4] = {0.f, 0.f, 0.f, 0.f}; s[t] = 1.f;
        fstep(m, s, 0.f, 0.f);
        sA[0*4 + t] = s[0]; sA[1*4 + t] = s[1]; sA[2*4 + t] = s[2]; sA[3*4 + t] = s[3];
    }
}

// ---------------------------------------------------------------------------
// x <- Am x + d  (tree-reduced, 12-cycle critical path)
// ---------------------------------------------------------------------------
#define MATVEC4(Am, d0, d1, d2, d3, x0_, x1_, x2_, x3_)                        \
    do {                                                                       \
        float n0 = fmaf((Am)[0],  (x0_), (Am)[1]  * (x1_)) +                   \
                   fmaf((Am)[2],  (x2_), fmaf((Am)[3],  (x3_), (d0)));         \
        float n1 = fmaf((Am)[4],  (x0_), (Am)[5]  * (x1_)) +                   \
                   fmaf((Am)[6],  (x2_), fmaf((Am)[7],  (x3_), (d1)));         \
        float n2 = fmaf((Am)[8],  (x0_), (Am)[9]  * (x1_)) +                   \
                   fmaf((Am)[10], (x2_), fmaf((Am)[11], (x3_), (d2)));         \
        float n3 = fmaf((Am)[12], (x0_), (Am)[13] * (x1_)) +                   \
                   fmaf((Am)[14], (x2_), fmaf((Am)[15], (x3_), (d3)));         \
        (x0_) = n0; (x1_) = n1; (x2_) = n2; (x3_) = n3;                        \
    } while (0)

// Cooperative 4x4 matmul + power (threads 0..15 of a warp)
__device__ __forceinline__ void coop_mm(float* R, const float* Pm, const float* Qm, int t) {
    if (t < 16) {
        int i = t >> 2, j = t & 3;
        R[t] = fmaf(Pm[i*4+0], Qm[0*4+j],
               fmaf(Pm[i*4+1], Qm[1*4+j],
               fmaf(Pm[i*4+2], Qm[2*4+j],
                    Pm[i*4+3] * Qm[3*4+j])));
    }
    __syncwarp();
}

__device__ void coop_pow(float* dst, const float* base, int e,
                         float* sP, float* sQ, float* sR, int t) {
    if (t < 16) {
        sP[t] = (t == 0 || t == 5 || t == 10 || t == 15) ? 1.f : 0.f;
        sQ[t] = base[t];
    }
    __syncwarp();
    while (e) {
        if (e & 1) {
            coop_mm(sR, sP, sQ, t);
            if (t < 16) sP[t] = sR[t];
            __syncwarp();
        }
        e >>= 1;
        if (e) {
            coop_mm(sR, sQ, sQ, t);
            if (t < 16) sQ[t] = sR[t];
            __syncwarp();
        }
    }
    if (t < 16) dst[t] = sP[t];
    __syncwarp();
}

// ---------------------------------------------------------------------------
// t_in: transpose u -> w_t = B u_t in chunk-minor float4 layout
//   block (32,8), tile = 32 chunks x 32 steps
// ---------------------------------------------------------------------------
__global__ void tin_kernel(const float2* __restrict__ u2,
                           const float* __restrict__ M, const float* __restrict__ C,
                           const float* __restrict__ K, const float* __restrict__ dtp,
                           int T) {
    __shared__ float4 s_t[32][33];
    __shared__ float sB[8];
    int tx = threadIdx.x, ty = threadIdx.y;

    if (ty == 0 && tx < 2) {      // B columns: step(0, e_tx)
        FSys m = mksys(M, C, K, dtp);
        float s[4] = {0.f, 0.f, 0.f, 0.f};
        fstep(m, s, tx == 0 ? 1.f : 0.f, tx == 1 ? 1.f : 0.f);
        sB[0*2 + tx] = s[0]; sB[1*2 + tx] = s[1];
        sB[2*2 + tx] = s[2]; sB[3*2 + tx] = s[3];
    }
    __syncthreads();

    float B0 = sB[0], B1 = sB[1], B2 = sB[2], B3 = sB[3];
    float B4 = sB[4], B5 = sB[5], B6 = sB[6], B7 = sB[7];

    int c0 = blockIdx.x * 32;
    int i0 = blockIdx.y * 32;

#pragma unroll
    for (int k = 0; k < 4; k++) {
        int cc = ty + 8 * k;
        int t = (c0 + cc) * L_CHUNK + i0 + tx;
        float2 uu = (t < T) ? u2[t] : make_float2(0.f, 0.f);
        float4 w;
        w.x = fmaf(B0, uu.x, B1 * uu.y);
        w.y = fmaf(B2, uu.x, B3 * uu.y);
        w.z = fmaf(B4, uu.x, B5 * uu.y);
        w.w = fmaf(B6, uu.x, B7 * uu.y);
        s_t[cc][tx] = w;
    }
    __syncthreads();

#pragma unroll
    for (int k = 0; k < 4; k++) {
        int di = ty + 8 * k;
        g_wt[(i0 + di) * NCPAD + c0 + tx] = s_t[tx][di];
    }
}

// ---------------------------------------------------------------------------
// phase1: per-chunk drive vector (zero IC), coalesced w loads
// ---------------------------------------------------------------------------
__global__ void phase1_kernel(const float* __restrict__ M, const float* __restrict__ C,
                              const float* __restrict__ K, const float* __restrict__ dtp,
                              int P) {
    __shared__ float sA[16];
    int tid = threadIdx.x;
    probe_A(sA, M, C, K, dtp, tid);
    __syncthreads();

    float A[16];
#pragma unroll
    for (int i = 0; i < 16; i++) A[i] = sA[i];

    int c = blockIdx.x * blockDim.x + tid;
    float x0 = 0.f, x1 = 0.f, x2 = 0.f, x3 = 0.f;
#pragma unroll 8
    for (int i = 0; i < L_CHUNK; i++) {
        float4 w = g_wt[i * NCPAD + c];
        MATVEC4(A, w.x, w.y, w.z, w.w, x0, x1, x2, x3);
    }
    if (c < P) {
        g_cd[c][0] = x0; g_cd[c][1] = x1; g_cd[c][2] = x2; g_cd[c][3] = x3;
    }
}

// ---------------------------------------------------------------------------
// phase2: in-kernel A + matrix powers, hierarchical boundary scan (1 warp)
// ---------------------------------------------------------------------------
__global__ void phase2_kernel(const float* __restrict__ M, const float* __restrict__ C,
                              const float* __restrict__ K, const float* __restrict__ x0in,
                              const float* __restrict__ dtp,
                              int P, int q, int r, int nact) {
    __shared__ float sA[16], sM[16], sMq[16], sMr[16], sP_[16], sQ_[16], sR_[16];
    __shared__ float s_e[32][4], s_x[32][4];
    int t = threadIdx.x;

    probe_A(sA, M, C, K, dtp, t);
    __syncwarp();
    coop_pow(sM,  sA, L_CHUNK, sP_, sQ_, sR_, t);   // M = A^L
    coop_pow(sMq, sM, q,       sP_, sQ_, sR_, t);   // M^q
    coop_pow(sMr, sM, r,       sP_, sQ_, sR_, t);   // M^r

    if (t == 0) {     // x0 layout [y1,v1,y2,v2] -> state [y1,y2,v1,v2]
        g_cx[0][0] = x0in[0];
        g_cx[0][1] = x0in[2];
        g_cx[0][2] = x0in[1];
        g_cx[0][3] = x0in[3];
    }
    __syncwarp();

    float Mm[16];
#pragma unroll
    for (int i = 0; i < 16; i++) Mm[i] = sM[i];

    int lo = t * q;
    int hi = lo + q; if (hi > P) hi = P;

    float e0 = 0.f, e1 = 0.f, e2 = 0.f, e3 = 0.f;
#pragma unroll 4
    for (int j = lo; j < hi; j++) {
        float d0 = g_cd[j][0], d1 = g_cd[j][1], d2 = g_cd[j][2], d3 = g_cd[j][3];
        MATVEC4(Mm, d0, d1, d2, d3, e0, e1, e2, e3);
    }
    s_e[t][0] = e0; s_e[t][1] = e1; s_e[t][2] = e2; s_e[t][3] = e3;
    __syncwarp();

    if (t == 0) {
        float x0 = g_cx[0][0], x1 = g_cx[0][1], x2 = g_cx[0][2], x3 = g_cx[0][3];
        for (int tt = 0; tt < nact; tt++) {
            s_x[tt][0] = x0; s_x[tt][1] = x1; s_x[tt][2] = x2; s_x[tt][3] = x3;
            float d0 = s_e[tt][0], d1 = s_e[tt][1], d2 = s_e[tt][2], d3 = s_e[tt][3];
            const float* MM = (tt == nact - 1) ? sMr : sMq;
            MATVEC4(MM, d0, d1, d2, d3, x0, x1, x2, x3);
        }
    }
    __syncwarp();

    if (lo < P) {
        float x0 = s_x[t][0], x1 = s_x[t][1], x2 = s_x[t][2], x3 = s_x[t][3];
#pragma unroll 4
        for (int j = lo; j < hi; j++) {
            float d0 = g_cd[j][0], d1 = g_cd[j][1], d2 = g_cd[j][2], d3 = g_cd[j][3];
            MATVEC4(Mm, d0, d1, d2, d3, x0, x1, x2, x3);
            g_cx[j+1][0] = x0; g_cx[j+1][1] = x1; g_cx[j+1][2] = x2; g_cx[j+1][3] = x3;
        }
    }
}

// ---------------------------------------------------------------------------
// phase3: replay; coalesced w loads; transposed output via smem buffer
//   128 threads = 128 chunks per block; 2 segments of 32 steps
// ---------------------------------------------------------------------------
__global__ void phase3_kernel(const float* __restrict__ M, const float* __restrict__ C,
                              const float* __restrict__ K, const float* __restrict__ dtp,
                              float4* __restrict__ out4, int T, int NC) {
    __shared__ float sA[16];
    __shared__ float2 s_z[32][129];
    int tid = threadIdx.x;
    probe_A(sA, M, C, K, dtp, tid);
    __syncthreads();

    float A[16];
#pragma unroll
    for (int i = 0; i < 16; i++) A[i] = sA[i];

    int c0 = blockIdx.x * 128;
    int c = c0 + tid;
    float x0 = 0.f, x1 = 0.f, x2 = 0.f, x3 = 0.f;
    if (c < NC) {
        x0 = g_cx[c][0]; x1 = g_cx[c][1]; x2 = g_cx[c][2]; x3 = g_cx[c][3];
    }

#pragma unroll
    for (int seg = 0; seg < 2; seg++) {
#pragma unroll 8
        for (int i2 = 0; i2 < 32; i2++) {
            float4 w = g_wt[(seg * 32 + i2) * NCPAD + c];
            MATVEC4(A, w.x, w.y, w.z, w.w, x0, x1, x2, x3);
            s_z[i2][tid] = make_float2(x0, x1);
        }
        __syncthreads();
        // dump 128 chunks x 32 steps as float4 (2 steps each), coalesced
#pragma unroll
        for (int j = 0; j < 16; j++) {
            int idx = tid + 128 * j;
            int dh = idx & 15, dc = idx >> 4;
            int tstep = (c0 + dc) * L_CHUNK + seg * 32 + 2 * dh;
            if (tstep < T) {
                float2 a = s_z[2*dh][dc];
                float2 b = s_z[2*dh + 1][dc];
                out4[((c0 + dc) << 5) + seg * 16 + dh] = make_float4(a.x, a.y, b.x, b.y);
            }
        }
        __syncthreads();
    }
}

// ---------------------------------------------------------------------------
// Launch
// ---------------------------------------------------------------------------
extern "C" void kernel_launch(void* const* d_in, const int* in_sizes, int n_in,
                              void* d_out, int out_size) {
    const float* u  = (const float*)d_in[0];
    const float* M  = (const float*)d_in[1];
    const float* C  = (const float*)d_in[2];
    const float* K  = (const float*)d_in[3];
    const float* x0 = (const float*)d_in[4];
    const float* dt = (const float*)d_in[5];

    int T  = in_sizes[0] / 2;
    int NC = (T + L_CHUNK - 1) / L_CHUNK;
    int P  = NC - 1;
    int q  = (P + 31) / 32; if (q < 1) q = 1;
    int nact = (P > 0) ? (P + q - 1) / q : 1;
    int r  = P - (nact - 1) * q; if (r < 1) r = 1;

    dim3 bt(32, 8);
    dim3 gt((NC + 31) / 32, L_CHUNK / 32);
    tin_kernel<<<gt, bt>>>((const float2*)u, M, C, K, dt, T);

    if (P > 0)
        phase1_kernel<<<(NC + 127) / 128, 128>>>(M, C, K, dt, P);
    phase2_kernel<<<1, 32>>>(M, C, K, x0, dt, P, q, r, nact);
    phase3_kernel<<<(NC + 127) / 128, 128>>>(M, C, K, dt, (float4*)d_out, T, NC);
}

// round 5
// speedup vs baseline: 1.0468x; 1.0468x over previous
#include <cuda_runtime.h>
#include <cuda_bf16.h>

// Blocked affine-scan RK4 integrator, v4.
// x_{t+1} = A x_t + B u_t exactly. L=16 -> 6250 parallel chunks, 3 kernels:
//   phase1: smem-tiled coalesced u load (contiguous per block!), w=Bu on the
//           fly, 16-step scan per thread -> per-chunk drive vector.
//   phase2: 128-lane hierarchical boundary scan (q=49) with in-kernel powers.
//   phase3: same tiling, replay from known start states, in-place smem
//           transpose of outputs, coalesced float4 stores. No global scratch
//           for u; the only intermediates are g_cd/g_cx (100 KB each).

#define L_CHUNK 16
#define CPB 64                      // chunks per block (phase1/phase3)
#define F4_PER_CHUNK (L_CHUNK / 2)  // 8 float4 of u per chunk
#define MAX_CHUNKS 8192

__device__ float4 g_cd[MAX_CHUNKS];      // per-chunk drive vectors
__device__ float4 g_cx[MAX_CHUNKS + 1];  // chunk start states

// ---------------------------------------------------------------------------
// fp32 RK4 step mirroring the reference arithmetic (basis probing only)
// ---------------------------------------------------------------------------
struct FSys { float Cm[4], Km[4], Md[2], dt; };

__device__ __forceinline__ FSys mksys(const float* M, const float* C,
                                      const float* K, const float* dtp) {
    FSys m;
    m.Md[0] = M[0]; m.Md[1] = M[1];
    float C0 = C[0], C1 = C[1], C2 = C[2];
    m.Cm[0] = C0 + C1; m.Cm[1] = -C1; m.Cm[2] = -C1; m.Cm[3] = C2 + C1;
    float K0 = K[0], K1 = K[1], K2 = K[2];
    m.Km[0] = K0 + K1; m.Km[1] = -K1; m.Km[2] = -K1; m.Km[3] = K2 + K1;
    m.dt = dtp[0];
    return m;
}

__device__ void fstep(const FSys& m, float s[4], float u0, float u1) {
    float dt = m.dt;
    float y0 = s[0], y1 = s[1], v0 = s[2], v1 = s[3];
#define ACC(z0, z1, w0, w1, a0, a1)                                             \
    a0 = (u0 - (m.Cm[0]*(w0) + m.Cm[1]*(w1)) - (m.Km[0]*(z0) + m.Km[1]*(z1))) / m.Md[0]; \
    a1 = (u1 - (m.Cm[2]*(w0) + m.Cm[3]*(w1)) - (m.Km[2]*(z0) + m.Km[3]*(z1))) / m.Md[1];
    float k1a, k1b; ACC(y0, y1, v0, v1, k1a, k1b);
    float y2a = y0 + v0*dt*0.5f, y2b = y1 + v1*dt*0.5f;
    float v2a = v0 + k1a*dt*0.5f, v2b = v1 + k1b*dt*0.5f;
    float k2a, k2b; ACC(y2a, y2b, v2a, v2b, k2a, k2b);
    float y3a = y0 + v2a*dt*0.5f, y3b = y1 + v2b*dt*0.5f;
    float v3a = v0 + k2a*dt*0.5f, v3b = v1 + k2b*dt*0.5f;
    float k3a, k3b; ACC(y3a, y3b, v3a, v3b, k3a, k3b);
    float y4a = y0 + v3a*dt, y4b = y1 + v3b*dt;
    float v4a = v0 + k3a*dt, v4b = v1 + k3b*dt;
    float k4a, k4b; ACC(y4a, y4b, v4a, v4b, k4a, k4b);
    (void)y2a; (void)y2b; (void)y3a; (void)y3b; (void)y4a; (void)y4b;
    s[0] = y0 + dt/6.f * (v0 + 2.f*v2a + 2.f*v3a + v4a);
    s[1] = y1 + dt/6.f * (v1 + 2.f*v2b + 2.f*v3b + v4b);
    s[2] = v0 + dt/6.f * (k1a + 2.f*k2a + 2.f*k3a + k4a);
    s[3] = v1 + dt/6.f * (k1b + 2.f*k2b + 2.f*k3b + k4b);
#undef ACC
}

// Probe A columns (threads 0..3) and B columns (threads 4..5) into smem.
__device__ __forceinline__ void probe_AB(float* sA, float* sB,
                                         const float* M, const float* C,
                                         const float* K, const float* dtp, int t) {
    if (t < 4) {
        FSys m = mksys(M, C, K, dtp);
        float s[4] = {0.f, 0.f, 0.f, 0.f}; s[t] = 1.f;
        fstep(m, s, 0.f, 0.f);
        sA[0*4 + t] = s[0]; sA[1*4 + t] = s[1]; sA[2*4 + t] = s[2]; sA[3*4 + t] = s[3];
    } else if (t < 6) {
        FSys m = mksys(M, C, K, dtp);
        int j = t - 4;
        float s[4] = {0.f, 0.f, 0.f, 0.f};
        fstep(m, s, j == 0 ? 1.f : 0.f, j == 1 ? 1.f : 0.f);
        sB[0*2 + j] = s[0]; sB[1*2 + j] = s[1]; sB[2*2 + j] = s[2]; sB[3*2 + j] = s[3];
    }
}

// ---------------------------------------------------------------------------
// x <- Am x + d  (tree-reduced, 12-cycle critical path)
// ---------------------------------------------------------------------------
#define MATVEC4(Am, d0, d1, d2, d3, x0_, x1_, x2_, x3_)                        \
    do {                                                                       \
        float n0 = fmaf((Am)[0],  (x0_), (Am)[1]  * (x1_)) +                   \
                   fmaf((Am)[2],  (x2_), fmaf((Am)[3],  (x3_), (d0)));         \
        float n1 = fmaf((Am)[4],  (x0_), (Am)[5]  * (x1_)) +                   \
                   fmaf((Am)[6],  (x2_), fmaf((Am)[7],  (x3_), (d1)));         \
        float n2 = fmaf((Am)[8],  (x0_), (Am)[9]  * (x1_)) +                   \
                   fmaf((Am)[10], (x2_), fmaf((Am)[11], (x3_), (d2)));         \
        float n3 = fmaf((Am)[12], (x0_), (Am)[13] * (x1_)) +                   \
                   fmaf((Am)[14], (x2_), fmaf((Am)[15], (x3_), (d3)));         \
        (x0_) = n0; (x1_) = n1; (x2_) = n2; (x3_) = n3;                        \
    } while (0)

// Cooperative 4x4 matmul + power (threads 0..15 of warp 0)
__device__ __forceinline__ void coop_mm(float* R, const float* Pm, const float* Qm, int t) {
    if (t < 16) {
        int i = t >> 2, j = t & 3;
        R[t] = fmaf(Pm[i*4+0], Qm[0*4+j],
               fmaf(Pm[i*4+1], Qm[1*4+j],
               fmaf(Pm[i*4+2], Qm[2*4+j],
                    Pm[i*4+3] * Qm[3*4+j])));
    }
    __syncwarp();
}

__device__ void coop_pow(float* dst, const float* base, int e,
                         float* sP, float* sQ, float* sR, int t) {
    if (t < 16) {
        sP[t] = (t == 0 || t == 5 || t == 10 || t == 15) ? 1.f : 0.f;
        sQ[t] = base[t];
    }
    __syncwarp();
    while (e) {
        if (e & 1) {
            coop_mm(sR, sP, sQ, t);
            if (t < 16) sP[t] = sR[t];
            __syncwarp();
        }
        e >>= 1;
        if (e) {
            coop_mm(sR, sQ, sQ, t);
            if (t < 16) sQ[t] = sR[t];
            __syncwarp();
        }
    }
    if (t < 16) dst[t] = sP[t];
    __syncwarp();
}

// ---------------------------------------------------------------------------
// phase1: coalesced tile load -> transpose in smem -> 16-step scan -> g_cd
// ---------------------------------------------------------------------------
__global__ void phase1_kernel(const float4* __restrict__ u4,
                              const float* __restrict__ M, const float* __restrict__ C,
                              const float* __restrict__ K, const float* __restrict__ dtp,
                              int P, int nf4) {
    __shared__ float sA[16], sB[8];
    __shared__ float2 s_u[L_CHUNK][CPB + 2];
    int tid = threadIdx.x;
    probe_AB(sA, sB, M, C, K, dtp, tid);

    int c0 = blockIdx.x * CPB;
    // stage: 512 float4 (contiguous region of u) -> transposed smem
#pragma unroll
    for (int k = 0; k < 8; k++) {
        int idx = tid + CPB * k;
        int g4 = c0 * F4_PER_CHUNK + idx;
        float4 q = (g4 < nf4) ? u4[g4] : make_float4(0.f, 0.f, 0.f, 0.f);
        int cc = idx >> 3, j = idx & 7;
        s_u[2*j][cc]     = make_float2(q.x, q.y);
        s_u[2*j + 1][cc] = make_float2(q.z, q.w);
    }
    __syncthreads();

    float A[16], B[8];
#pragma unroll
    for (int i = 0; i < 16; i++) A[i] = sA[i];
#pragma unroll
    for (int i = 0; i < 8; i++) B[i] = sB[i];

    float x0 = 0.f, x1 = 0.f, x2 = 0.f, x3 = 0.f;
#pragma unroll
    for (int i = 0; i < L_CHUNK; i++) {
        float2 uu = s_u[i][tid];
        float w0 = fmaf(B[0], uu.x, B[1] * uu.y);
        float w1 = fmaf(B[2], uu.x, B[3] * uu.y);
        float w2 = fmaf(B[4], uu.x, B[5] * uu.y);
        float w3 = fmaf(B[6], uu.x, B[7] * uu.y);
        MATVEC4(A, w0, w1, w2, w3, x0, x1, x2, x3);
    }
    int c = c0 + tid;
    if (c < P) g_cd[c] = make_float4(x0, x1, x2, x3);
}

// ---------------------------------------------------------------------------
// phase2: 128-lane hierarchical boundary scan, in-kernel matrix powers
// ---------------------------------------------------------------------------
__global__ void phase2_kernel(const float* __restrict__ M, const float* __restrict__ C,
                              const float* __restrict__ K, const float* __restrict__ x0in,
                              const float* __restrict__ dtp,
                              int P, int q, int r, int nact) {
    __shared__ float sA[16], sB[8], sM[16], sMq[16], sMr[16], sP_[16], sQ_[16], sR_[16];
    __shared__ float4 s_e[128], s_x[128];
    int t = threadIdx.x;

    probe_AB(sA, sB, M, C, K, dtp, t);
    __syncthreads();
    if (t < 32) {
        coop_pow(sM,  sA, L_CHUNK, sP_, sQ_, sR_, t);   // M = A^L
        coop_pow(sMq, sM, q,       sP_, sQ_, sR_, t);   // M^q
        coop_pow(sMr, sM, r,       sP_, sQ_, sR_, t);   // M^r
    }
    __syncthreads();

    float Mm[16];
#pragma unroll
    for (int i = 0; i < 16; i++) Mm[i] = sM[i];

    int lo = t * q;
    int hi = lo + q; if (hi > P) hi = P;

    float e0 = 0.f, e1 = 0.f, e2 = 0.f, e3 = 0.f;
#pragma unroll 4
    for (int j = lo; j < hi; j++) {
        float4 d = g_cd[j];
        MATVEC4(Mm, d.x, d.y, d.z, d.w, e0, e1, e2, e3);
    }
    s_e[t] = make_float4(e0, e1, e2, e3);
    __syncthreads();

    if (t == 0) {
        float Mq[16], Mr[16];
#pragma unroll
        for (int i = 0; i < 16; i++) { Mq[i] = sMq[i]; Mr[i] = sMr[i]; }
        // x0 layout [y1,v1,y2,v2] -> state [y1,y2,v1,v2]
        float x0 = x0in[0], x1 = x0in[2], x2 = x0in[1], x3 = x0in[3];
        g_cx[0] = make_float4(x0, x1, x2, x3);
        for (int tt = 0; tt < nact; tt++) {
            s_x[tt] = make_float4(x0, x1, x2, x3);
            float4 d = s_e[tt];
            const float* MM = (tt == nact - 1) ? Mr : Mq;
            MATVEC4(MM, d.x, d.y, d.z, d.w, x0, x1, x2, x3);
        }
    }
    __syncthreads();

    if (lo < P) {
        float4 xx = s_x[t];
        float x0 = xx.x, x1 = xx.y, x2 = xx.z, x3 = xx.w;
#pragma unroll 4
        for (int j = lo; j < hi; j++) {
            float4 d = g_cd[j];
            MATVEC4(Mm, d.x, d.y, d.z, d.w, x0, x1, x2, x3);
            g_cx[j + 1] = make_float4(x0, x1, x2, x3);
        }
    }
}

// ---------------------------------------------------------------------------
// phase3: replay from start states; output transposed in-place in the tile
// ---------------------------------------------------------------------------
__global__ void phase3_kernel(const float4* __restrict__ u4, float4* __restrict__ out4,
                              const float* __restrict__ M, const float* __restrict__ C,
                              const float* __restrict__ K, const float* __restrict__ dtp,
                              int NC, int nf4) {
    __shared__ float sA[16], sB[8];
    __shared__ float2 s_u[L_CHUNK][CPB + 2];
    int tid = threadIdx.x;
    probe_AB(sA, sB, M, C, K, dtp, tid);

    int c0 = blockIdx.x * CPB;
#pragma unroll
    for (int k = 0; k < 8; k++) {
        int idx = tid + CPB * k;
        int g4 = c0 * F4_PER_CHUNK + idx;
        float4 q = (g4 < nf4) ? u4[g4] : make_float4(0.f, 0.f, 0.f, 0.f);
        int cc = idx >> 3, j = idx & 7;
        s_u[2*j][cc]     = make_float2(q.x, q.y);
        s_u[2*j + 1][cc] = make_float2(q.z, q.w);
    }
    __syncthreads();

    float A[16], B[8];
#pragma unroll
    for (int i = 0; i < 16; i++) A[i] = sA[i];
#pragma unroll
    for (int i = 0; i < 8; i++) B[i] = sB[i];

    int c = c0 + tid;
    float x0 = 0.f, x1 = 0.f, x2 = 0.f, x3 = 0.f;
    if (c < NC) {
        float4 xx = g_cx[c];
        x0 = xx.x; x1 = xx.y; x2 = xx.z; x3 = xx.w;
    }

    // scan; each thread reads/writes only its own column -> no sync needed
#pragma unroll
    for (int i = 0; i < L_CHUNK; i++) {
        float2 uu = s_u[i][tid];
        float w0 = fmaf(B[0], uu.x, B[1] * uu.y);
        float w1 = fmaf(B[2], uu.x, B[3] * uu.y);
        float w2 = fmaf(B[4], uu.x, B[5] * uu.y);
        float w3 = fmaf(B[6], uu.x, B[7] * uu.y);
        MATVEC4(A, w0, w1, w2, w3, x0, x1, x2, x3);
        s_u[i][tid] = make_float2(x0, x1);   // positions after the step
    }
    __syncthreads();

    // coalesced transposed store (contiguous output region per block)
#pragma unroll
    for (int k = 0; k < 8; k++) {
        int idx = tid + CPB * k;
        int g4 = c0 * F4_PER_CHUNK + idx;
        if (g4 < nf4) {
            int cc = idx >> 3, j = idx & 7;
            float2 a = s_u[2*j][cc];
            float2 b = s_u[2*j + 1][cc];
            out4[g4] = make_float4(a.x, a.y, b.x, b.y);
        }
    }
}

// ---------------------------------------------------------------------------
// Launch
// ---------------------------------------------------------------------------
extern "C" void kernel_launch(void* const* d_in, const int* in_sizes, int n_in,
                              void* d_out, int out_size) {
    const float* u  = (const float*)d_in[0];
    const float* M  = (const float*)d_in[1];
    const float* C  = (const float*)d_in[2];
    const float* K  = (const float*)d_in[3];
    const float* x0 = (const float*)d_in[4];
    const float* dt = (const float*)d_in[5];

    int T  = in_sizes[0] / 2;
    int NC = (T + L_CHUNK - 1) / L_CHUNK;
    int P  = NC - 1;
    int q  = (P + 127) / 128; if (q < 1) q = 1;
    int nact = (P > 0) ? (P + q - 1) / q : 1;
    int r  = P - (nact - 1) * q; if (r < 1) r = 1;
    int nf4 = (2 * T) / 4;
    int nb  = (NC + CPB - 1) / CPB;

    if (P > 0) {
        phase1_kernel<<<nb, CPB>>>((const float4*)u, M, C, K, dt, P, nf4);
        phase2_kernel<<<1, 128>>>(M, C, K, x0, dt, P, q, r, nact);
    }
    phase3_kernel<<<nb, CPB>>>((const float4*)u, (float4*)d_out, M, C, K, dt, NC, nf4);
}